// round 15
// baseline (speedup 1.0000x reference)
#include <cuda_runtime.h>
#include <cuda_fp16.h>
#include <cstdint>

// ---------------------------------------------------------------------------
// QuantLinear: out[M,N] = x[M,K] @ dequant(qweight)[K,N] + bias[N]
// M=4096, K=4096, N=11008.  compute_103 PTX => HMMA mma.sync path.
//
// Launch 1 (prep): convx + transposed dequant + zero-init of remainder tiles.
// Launch 2 (gemm): 128x128 tile, BK=64, 3-stage mbarrier ring, 256 thr,
//          warp tile 64x32, 2 CTAs/SM, A-ldsm/MMA interleave (R14 structure).
//          Tiles 0..2663 one CTA each; tiles 2664..2751 split-K=2 with
//          atomicAdd combine.
//          NEW: per-thread copy offsets (swizzle + global) hoisted out of
//          the chunk loop; refill path is 8x (add + cp.async).
// ---------------------------------------------------------------------------

#define M_DIM 4096
#define K_DIM 4096
#define N_DIM 11008

#define BM 128
#define BN 128
#define BK 64
#define STAGES 3
#define KCHUNKS (K_DIM / BK)            // 64
#define NTILES ((M_DIM / BM) * (N_DIM / BN))          // 2752
#define NORMAL_TILES 2664               // 9 * 296
#define REM_TILES (NTILES - NORMAL_TILES)             // 88
#define GEMM_GRID (NORMAL_TILES + 2 * REM_TILES)      // 2840
#define A_STAGE_BYTES (BM * 128)        // 16384
#define B_STAGE_BYTES (BN * 128)        // 16384
#define STAGE_BYTES (A_STAGE_BYTES + B_STAGE_BYTES)   // 32768
#define SMEM_TOTAL (1024 + STAGES * STAGE_BYTES)      // 99328

#define CONVX_BLOCKS (M_DIM * K_DIM / 1024)           // 16384
#define DQ_KP_BLKS (K_DIM / 8 / 32)                   // 16
#define DQ_N_BLKS (N_DIM / 64)                        // 172
#define DQ_BLOCKS (DQ_KP_BLKS * DQ_N_BLKS)            // 2752
#define ZERO_BLOCKS (REM_TILES * 16)                  // 1408
#define DQ_SMEM (64 * 33 * 16)                        // 33792 B

__device__ __half g_Wt[(size_t)N_DIM * K_DIM];  // [N][K]
__device__ __half g_Xh[(size_t)M_DIM * K_DIM];  // [M][K]

// ---------------------------------------------------------------------------
__device__ __forceinline__ uint32_t smem_u32(const void* p) {
    uint32_t a;
    asm("{ .reg .u64 t; cvta.to.shared.u64 t, %1; cvt.u32.u64 %0, t; }"
        : "=r"(a) : "l"(p));
    return a;
}

#define CP_ASYNC16(smem_addr, gptr) \
    asm volatile("cp.async.cg.shared.global [%0], [%1], 16;" \
        :: "r"(smem_addr), "l"(__cvta_generic_to_global(gptr)) : "memory")

#define MBARRIER_INIT(addr, cnt) \
    asm volatile("mbarrier.init.shared.b64 [%0], %1;" :: "r"(addr), "r"(cnt) : "memory")

#define CP_ARRIVE_NOINC(addr) \
    asm volatile("cp.async.mbarrier.arrive.noinc.shared.b64 [%0];" \
        :: "r"(addr) : "memory")

#define MBARRIER_ARRIVE(addr) \
    asm volatile("mbarrier.arrive.shared.b64 _, [%0];" :: "r"(addr) : "memory")

__device__ __forceinline__ void mbar_wait(uint32_t mbar, uint32_t phase) {
    asm volatile(
        "{\n\t"
        ".reg .pred P;\n\t"
        "LAB_WAIT_%=:\n\t"
        "mbarrier.try_wait.parity.shared.b64 P, [%0], %1, 0x989680;\n\t"
        "@P bra.uni LAB_DONE_%=;\n\t"
        "bra.uni LAB_WAIT_%=;\n\t"
        "LAB_DONE_%=:\n\t"
        "}"
        :: "r"(mbar), "r"(phase) : "memory");
}

__device__ __forceinline__ void ldsm_x4(uint32_t& r0, uint32_t& r1,
                                        uint32_t& r2, uint32_t& r3, uint32_t addr) {
    asm volatile("ldmatrix.sync.aligned.m8n8.x4.shared.b16 {%0,%1,%2,%3}, [%4];"
                 : "=r"(r0), "=r"(r1), "=r"(r2), "=r"(r3) : "r"(addr));
}

__device__ __forceinline__ void mma_16816(float* c, const uint32_t* a, const uint32_t* b) {
    asm volatile(
        "mma.sync.aligned.m16n8k16.row.col.f32.f16.f16.f32 "
        "{%0,%1,%2,%3}, {%4,%5,%6,%7}, {%8,%9}, {%0,%1,%2,%3};"
        : "+f"(c[0]), "+f"(c[1]), "+f"(c[2]), "+f"(c[3])
        : "r"(a[0]), "r"(a[1]), "r"(a[2]), "r"(a[3]), "r"(b[0]), "r"(b[1]));
}

// ---------------------------------------------------------------------------
// Launch 1: fused prep (convx + transposed dequant + remainder-tile zeroing).
// ---------------------------------------------------------------------------
__global__ void __launch_bounds__(256)
prep_kernel(const float* __restrict__ x,
            const int* __restrict__ qw,
            const float* __restrict__ sc,
            const int* __restrict__ qz,
            float* __restrict__ out) {
    extern __shared__ uint4 ds[];   // [64 n][33 kp] 16B entries (dequant only)
    int b = blockIdx.x;
    int tid = threadIdx.x;

    if (b < CONVX_BLOCKS) {
        size_t i = ((size_t)b * 256 + tid) * 4;
        float4 v = *reinterpret_cast<const float4*>(x + i);
        __half2 a = __floats2half2_rn(v.x, v.y);
        __half2 c = __floats2half2_rn(v.z, v.w);
        uint2 u;
        u.x = *reinterpret_cast<uint32_t*>(&a);
        u.y = *reinterpret_cast<uint32_t*>(&c);
        *reinterpret_cast<uint2*>(&g_Xh[i]) = u;
        return;
    }

    if (b >= CONVX_BLOCKS + DQ_BLOCKS) {
        int zb = b - CONVX_BLOCKS - DQ_BLOCKS;   // 0..1407
        int gt = NORMAL_TILES + (zb >> 4);
        int within = zb & 15;
        int m0 = (gt & 31) * BM;
        int n0 = (gt >> 5) * BN;
        int idx = within * 1024 + tid * 4;
        int r = idx >> 7, c = idx & 127;
        float4 z = {0.f, 0.f, 0.f, 0.f};
        *reinterpret_cast<float4*>(out + (size_t)(m0 + r) * N_DIM + n0 + c) = z;
        return;
    }

    int db = b - CONVX_BLOCKS;
    int kp0 = (db % DQ_KP_BLKS) * 32;
    int n0  = (db / DQ_KP_BLKS) * 64;

#pragma unroll
    for (int i = 0; i < 8; i++) {
        int idx = i * 256 + tid;
        int nl = idx & 63, kl = idx >> 6;   // kl 0..31
        int kp = kp0 + kl;
        int n  = n0 + nl;
        int w32 = qw[(size_t)kp * N_DIM + n];
        int g = kp >> 4;
        float s = sc[(size_t)g * N_DIM + n];
        int zw = qz[(size_t)g * (N_DIM / 8) + (n >> 3)];
        int zq = ((zw >> ((n & 7) * 4)) & 15) + 1;
        __half2 h[4];
#pragma unroll
        for (int j = 0; j < 4; j++) {
            float v0 = s * (float)(((w32 >> (8 * j))     & 15) - zq);
            float v1 = s * (float)(((w32 >> (8 * j + 4)) & 15) - zq);
            h[j] = __floats2half2_rn(v0, v1);
        }
        ds[nl * 33 + kl] = *reinterpret_cast<uint4*>(h);
    }
    __syncthreads();
#pragma unroll
    for (int i = 0; i < 8; i++) {
        int idx = i * 256 + tid;
        int nl = idx >> 5, kl = idx & 31;   // nl 0..63
        *reinterpret_cast<uint4*>(
            &g_Wt[(size_t)(n0 + nl) * K_DIM + (size_t)(kp0 + kl) * 8]) =
            ds[nl * 33 + kl];
    }
}

// ---------------------------------------------------------------------------
// Launch 2: GEMM + split-K remainder (R14 structure + hoisted copy offsets).
// ---------------------------------------------------------------------------
__device__ __forceinline__ void copy_stage(uint32_t dst,
                                           const char* pA, const char* pB,
                                           const uint32_t* swv,
                                           const uint32_t* gofs) {
#pragma unroll
    for (int i = 0; i < 4; i++) {
        CP_ASYNC16(dst + swv[i], pA + gofs[i]);
    }
#pragma unroll
    for (int i = 0; i < 4; i++) {
        CP_ASYNC16(dst + A_STAGE_BYTES + swv[i], pB + gofs[i]);
    }
}

__global__ void __launch_bounds__(256, 2)
gemm_kernel(const float* __restrict__ bias, float* __restrict__ out) {
    extern __shared__ __align__(1024) char smem[];
    uint32_t sb = smem_u32(smem);
    const uint32_t data0 = sb + 1024;

    int tid = threadIdx.x;
    int wid = tid >> 5, lane = tid & 31;
    int warp_m = wid & 1;
    int warp_n = wid >> 1;

    int bid = blockIdx.x;
    bool is_rem = bid >= NORMAL_TILES;
    int ri = bid - NORMAL_TILES;
    int gt = is_rem ? NORMAL_TILES + (ri % REM_TILES) : bid;
    int khalf = is_rem ? (ri / REM_TILES) : 0;
    int nchunks = is_rem ? 32 : 64;
    int kc0 = khalf * 32;

    int m_base = (gt & 31) * BM;
    int n_base = (gt >> 5) * BN;

    // hoisted per-thread copy offsets (identical tables for A and B)
    uint32_t swv[4], gofs[4];
#pragma unroll
    for (int i = 0; i < 4; i++) {
        int c = tid + i * 256;
        int row = c >> 3, col = (c & 7) * 16;
        swv[i]  = (uint32_t)(row * 128 + (col ^ ((row & 7) << 4)));
        gofs[i] = (uint32_t)(row * (K_DIM * 2) + col);
    }
    const char* baseA = (const char*)(g_Xh + (size_t)m_base * K_DIM) + kc0 * 128;
    const char* baseB = (const char*)(g_Wt + (size_t)n_base * K_DIM) + kc0 * 128;

    if (tid == 0) {
#pragma unroll
        for (int s = 0; s < STAGES; s++) {
            MBARRIER_INIT(sb + s * 8, 256);       // full
            MBARRIER_INIT(sb + 32 + s * 8, 8);    // empty
        }
    }
    __syncthreads();

    // prologue: chunks kc0 .. kc0+2
#pragma unroll
    for (int s = 0; s < STAGES; s++) {
        copy_stage(data0 + s * STAGE_BYTES, baseA + s * 128, baseB + s * 128,
                   swv, gofs);
        CP_ARRIVE_NOINC(sb + s * 8);
    }

    float acc[4][4][4];
#pragma unroll
    for (int i = 0; i < 4; i++)
#pragma unroll
        for (int j = 0; j < 4; j++)
#pragma unroll
            for (int c = 0; c < 4; c++) acc[i][j][c] = 0.0f;

    const int a_row0 = warp_m * 64 + (lane & 15);
    const int a_col0 = (lane >> 4) * 16;
    const int b_row0 = warp_n * 32 + ((lane >> 4) << 3) + (lane & 7);
    const int b_col0 = ((lane >> 3) & 1) * 16;

    int s = 0;
    uint32_t ph = 0;
    // running pointers for refill (chunk kt+STAGES), advance 128 B per chunk
    const char* pA = baseA + STAGES * 128;
    const char* pB = baseB + STAGES * 128;

    for (int kt = 0; kt < nchunks; kt++) {
        mbar_wait(sb + s * 8, ph);   // full[s]

        uint32_t sA = data0 + s * STAGE_BYTES;
        uint32_t sB = sA + A_STAGE_BYTES;

#pragma unroll
        for (int k16 = 0; k16 < 4; k16++) {
            // B fragments first (shared by all mi)
            uint32_t b[4][2];
#pragma unroll
            for (int j = 0; j < 2; j++) {
                int row = b_row0 + j * 16;
                int col = b_col0 + k16 * 32;
                uint32_t addr = sB + row * 128 + (col ^ ((row & 7) << 4));
                ldsm_x4(b[2 * j][0], b[2 * j][1], b[2 * j + 1][0], b[2 * j + 1][1], addr);
            }
            // interleave: per mi, load A fragment then run its 4 MMAs
#pragma unroll
            for (int mi = 0; mi < 4; mi++) {
                uint32_t a[4];
                int row = a_row0 + mi * 16;
                int col = a_col0 + k16 * 32;
                uint32_t addr = sA + row * 128 + (col ^ ((row & 7) << 4));
                ldsm_x4(a[0], a[1], a[2], a[3], addr);
                if (k16 == 3 && mi == 3 && lane == 0) {
                    MBARRIER_ARRIVE(sb + 32 + s * 8);   // empty[s]: all reads done
                }
#pragma unroll
                for (int nj = 0; nj < 4; nj++)
                    mma_16816(acc[mi][nj], a, b[nj]);
            }
        }

        if (kt + STAGES < nchunks) {
            mbar_wait(sb + 32 + s * 8, ph);   // empty[s]
            copy_stage(data0 + s * STAGE_BYTES, pA, pB, swv, gofs);
            CP_ARRIVE_NOINC(sb + s * 8);
        }
        pA += 128;
        pB += 128;

        s++;
        if (s == STAGES) { s = 0; ph ^= 1; }
    }

    // epilogue
    const int m0 = m_base + warp_m * 64;
    const int n0 = n_base + warp_n * 32;
    if (!is_rem) {
#pragma unroll
        for (int mi = 0; mi < 4; mi++) {
#pragma unroll
            for (int nj = 0; nj < 4; nj++) {
                int m = m0 + mi * 16 + (lane >> 2);
                int n = n0 + nj * 8 + (lane & 3) * 2;
                float2 b2 = *reinterpret_cast<const float2*>(bias + n);
                float2 o0, o1;
                o0.x = acc[mi][nj][0] + b2.x;
                o0.y = acc[mi][nj][1] + b2.y;
                o1.x = acc[mi][nj][2] + b2.x;
                o1.y = acc[mi][nj][3] + b2.y;
                *reinterpret_cast<float2*>(out + (size_t)m * N_DIM + n) = o0;
                *reinterpret_cast<float2*>(out + (size_t)(m + 8) * N_DIM + n) = o1;
            }
        }
    } else {
        float bw = (khalf == 0) ? 1.0f : 0.0f;
#pragma unroll
        for (int mi = 0; mi < 4; mi++) {
#pragma unroll
            for (int nj = 0; nj < 4; nj++) {
                int m = m0 + mi * 16 + (lane >> 2);
                int n = n0 + nj * 8 + (lane & 3) * 2;
                float2 b2 = *reinterpret_cast<const float2*>(bias + n);
                atomicAdd(out + (size_t)m * N_DIM + n,     acc[mi][nj][0] + bw * b2.x);
                atomicAdd(out + (size_t)m * N_DIM + n + 1, acc[mi][nj][1] + bw * b2.y);
                atomicAdd(out + (size_t)(m + 8) * N_DIM + n,     acc[mi][nj][2] + bw * b2.x);
                atomicAdd(out + (size_t)(m + 8) * N_DIM + n + 1, acc[mi][nj][3] + bw * b2.y);
            }
        }
    }
}

// ---------------------------------------------------------------------------
extern "C" void kernel_launch(void* const* d_in, const int* in_sizes, int n_in,
                              void* d_out, int out_size) {
    const float* x    = (const float*)d_in[0];
    const int*   qw   = (const int*)d_in[1];
    const float* sc   = (const float*)d_in[2];
    const int*   qz   = (const int*)d_in[3];
    // d_in[4] = g_idx (identity k/128 grouping; folded into index math)
    const float* bias = (const float*)d_in[5];
    float* out = (float*)d_out;

    cudaFuncSetAttribute(prep_kernel, cudaFuncAttributeMaxDynamicSharedMemorySize,
                         DQ_SMEM);
    prep_kernel<<<CONVX_BLOCKS + DQ_BLOCKS + ZERO_BLOCKS, 256, DQ_SMEM>>>(
        x, qw, sc, qz, out);

    cudaFuncSetAttribute(gemm_kernel, cudaFuncAttributeMaxDynamicSharedMemorySize,
                         SMEM_TOTAL);
    gemm_kernel<<<GEMM_GRID, 256, SMEM_TOTAL>>>(bias, out);
}

// round 16
// speedup vs baseline: 1.5612x; 1.5612x over previous
#include <cuda_runtime.h>
#include <cuda_fp16.h>
#include <cstdint>

// ---------------------------------------------------------------------------
// QuantLinear: out[M,N] = x[M,K] @ dequant(qweight)[K,N] + bias[N]
// M=4096, K=4096, N=11008.  compute_103 PTX => HMMA mma.sync path.
//
// FINAL (R14-proven, 793.6us):
// Launch 1 (prep): convx + transposed dequant + zero-init of remainder tiles.
// Launch 2 (gemm): 128x128 tile, BK=64, 3-stage mbarrier ring, 256 thr,
//          warp tile 64x32, 2 CTAs/SM, A-ldsm/MMA interleave.
//          Tiles 0..2663 one CTA each; tiles 2664..2751 split-K=2 with
//          atomicAdd combine.
// ---------------------------------------------------------------------------

#define M_DIM 4096
#define K_DIM 4096
#define N_DIM 11008

#define BM 128
#define BN 128
#define BK 64
#define STAGES 3
#define KCHUNKS (K_DIM / BK)            // 64
#define NTILES ((M_DIM / BM) * (N_DIM / BN))          // 2752
#define NORMAL_TILES 2664               // 9 * 296
#define REM_TILES (NTILES - NORMAL_TILES)             // 88
#define GEMM_GRID (NORMAL_TILES + 2 * REM_TILES)      // 2840
#define A_STAGE_BYTES (BM * 128)        // 16384
#define B_STAGE_BYTES (BN * 128)        // 16384
#define STAGE_BYTES (A_STAGE_BYTES + B_STAGE_BYTES)   // 32768
#define SMEM_TOTAL (1024 + STAGES * STAGE_BYTES)      // 99328

#define CONVX_BLOCKS (M_DIM * K_DIM / 1024)           // 16384
#define DQ_KP_BLKS (K_DIM / 8 / 32)                   // 16
#define DQ_N_BLKS (N_DIM / 64)                        // 172
#define DQ_BLOCKS (DQ_KP_BLKS * DQ_N_BLKS)            // 2752
#define ZERO_BLOCKS (REM_TILES * 16)                  // 1408
#define DQ_SMEM (64 * 33 * 16)                        // 33792 B

__device__ __half g_Wt[(size_t)N_DIM * K_DIM];  // [N][K]
__device__ __half g_Xh[(size_t)M_DIM * K_DIM];  // [M][K]

// ---------------------------------------------------------------------------
__device__ __forceinline__ uint32_t smem_u32(const void* p) {
    uint32_t a;
    asm("{ .reg .u64 t; cvta.to.shared.u64 t, %1; cvt.u32.u64 %0, t; }"
        : "=r"(a) : "l"(p));
    return a;
}

#define CP_ASYNC16(smem_addr, gptr) \
    asm volatile("cp.async.cg.shared.global [%0], [%1], 16;" \
        :: "r"(smem_addr), "l"(__cvta_generic_to_global(gptr)) : "memory")

#define MBARRIER_INIT(addr, cnt) \
    asm volatile("mbarrier.init.shared.b64 [%0], %1;" :: "r"(addr), "r"(cnt) : "memory")

#define CP_ARRIVE_NOINC(addr) \
    asm volatile("cp.async.mbarrier.arrive.noinc.shared.b64 [%0];" \
        :: "r"(addr) : "memory")

#define MBARRIER_ARRIVE(addr) \
    asm volatile("mbarrier.arrive.shared.b64 _, [%0];" :: "r"(addr) : "memory")

__device__ __forceinline__ void mbar_wait(uint32_t mbar, uint32_t phase) {
    asm volatile(
        "{\n\t"
        ".reg .pred P;\n\t"
        "LAB_WAIT_%=:\n\t"
        "mbarrier.try_wait.parity.shared.b64 P, [%0], %1, 0x989680;\n\t"
        "@P bra.uni LAB_DONE_%=;\n\t"
        "bra.uni LAB_WAIT_%=;\n\t"
        "LAB_DONE_%=:\n\t"
        "}"
        :: "r"(mbar), "r"(phase) : "memory");
}

__device__ __forceinline__ void ldsm_x4(uint32_t& r0, uint32_t& r1,
                                        uint32_t& r2, uint32_t& r3, uint32_t addr) {
    asm volatile("ldmatrix.sync.aligned.m8n8.x4.shared.b16 {%0,%1,%2,%3}, [%4];"
                 : "=r"(r0), "=r"(r1), "=r"(r2), "=r"(r3) : "r"(addr));
}

__device__ __forceinline__ void mma_16816(float* c, const uint32_t* a, const uint32_t* b) {
    asm volatile(
        "mma.sync.aligned.m16n8k16.row.col.f32.f16.f16.f32 "
        "{%0,%1,%2,%3}, {%4,%5,%6,%7}, {%8,%9}, {%0,%1,%2,%3};"
        : "+f"(c[0]), "+f"(c[1]), "+f"(c[2]), "+f"(c[3])
        : "r"(a[0]), "r"(a[1]), "r"(a[2]), "r"(a[3]), "r"(b[0]), "r"(b[1]));
}

// ---------------------------------------------------------------------------
// Launch 1: fused prep (convx + transposed dequant + remainder-tile zeroing).
// ---------------------------------------------------------------------------
__global__ void __launch_bounds__(256)
prep_kernel(const float* __restrict__ x,
            const int* __restrict__ qw,
            const float* __restrict__ sc,
            const int* __restrict__ qz,
            float* __restrict__ out) {
    extern __shared__ uint4 ds[];   // [64 n][33 kp] 16B entries (dequant only)
    int b = blockIdx.x;
    int tid = threadIdx.x;

    if (b < CONVX_BLOCKS) {
        size_t i = ((size_t)b * 256 + tid) * 4;
        float4 v = *reinterpret_cast<const float4*>(x + i);
        __half2 a = __floats2half2_rn(v.x, v.y);
        __half2 c = __floats2half2_rn(v.z, v.w);
        uint2 u;
        u.x = *reinterpret_cast<uint32_t*>(&a);
        u.y = *reinterpret_cast<uint32_t*>(&c);
        *reinterpret_cast<uint2*>(&g_Xh[i]) = u;
        return;
    }

    if (b >= CONVX_BLOCKS + DQ_BLOCKS) {
        int zb = b - CONVX_BLOCKS - DQ_BLOCKS;   // 0..1407
        int gt = NORMAL_TILES + (zb >> 4);
        int within = zb & 15;
        int m0 = (gt & 31) * BM;
        int n0 = (gt >> 5) * BN;
        int idx = within * 1024 + tid * 4;
        int r = idx >> 7, c = idx & 127;
        float4 z = {0.f, 0.f, 0.f, 0.f};
        *reinterpret_cast<float4*>(out + (size_t)(m0 + r) * N_DIM + n0 + c) = z;
        return;
    }

    int db = b - CONVX_BLOCKS;
    int kp0 = (db % DQ_KP_BLKS) * 32;
    int n0  = (db / DQ_KP_BLKS) * 64;

#pragma unroll
    for (int i = 0; i < 8; i++) {
        int idx = i * 256 + tid;
        int nl = idx & 63, kl = idx >> 6;   // kl 0..31
        int kp = kp0 + kl;
        int n  = n0 + nl;
        int w32 = qw[(size_t)kp * N_DIM + n];
        int g = kp >> 4;
        float s = sc[(size_t)g * N_DIM + n];
        int zw = qz[(size_t)g * (N_DIM / 8) + (n >> 3)];
        int zq = ((zw >> ((n & 7) * 4)) & 15) + 1;
        __half2 h[4];
#pragma unroll
        for (int j = 0; j < 4; j++) {
            float v0 = s * (float)(((w32 >> (8 * j))     & 15) - zq);
            float v1 = s * (float)(((w32 >> (8 * j + 4)) & 15) - zq);
            h[j] = __floats2half2_rn(v0, v1);
        }
        ds[nl * 33 + kl] = *reinterpret_cast<uint4*>(h);
    }
    __syncthreads();
#pragma unroll
    for (int i = 0; i < 8; i++) {
        int idx = i * 256 + tid;
        int nl = idx >> 5, kl = idx & 31;   // nl 0..63
        *reinterpret_cast<uint4*>(
            &g_Wt[(size_t)(n0 + nl) * K_DIM + (size_t)(kp0 + kl) * 8]) =
            ds[nl * 33 + kl];
    }
}

// ---------------------------------------------------------------------------
// Launch 2: GEMM + split-K remainder (R14 structure).
// ---------------------------------------------------------------------------
__device__ __forceinline__ void copy_stage(uint32_t dst, int m_base, int n_base,
                                           int k0, int tid) {
    const __half* Ab = g_Xh + (size_t)m_base * K_DIM + k0;
    const __half* Bb = g_Wt + (size_t)n_base * K_DIM + k0;
#pragma unroll
    for (int i = 0; i < 4; i++) {
        int c = tid + i * 256;
        int row = c >> 3, col = (c & 7) * 16;
        uint32_t sw = (uint32_t)(row * 128 + (col ^ ((row & 7) << 4)));
        CP_ASYNC16(dst + sw, (const char*)Ab + (size_t)row * (K_DIM * 2) + col);
    }
#pragma unroll
    for (int i = 0; i < 4; i++) {
        int c = tid + i * 256;
        int row = c >> 3, col = (c & 7) * 16;
        uint32_t sw = (uint32_t)(row * 128 + (col ^ ((row & 7) << 4)));
        CP_ASYNC16(dst + A_STAGE_BYTES + sw,
                   (const char*)Bb + (size_t)row * (K_DIM * 2) + col);
    }
}

__global__ void __launch_bounds__(256, 2)
gemm_kernel(const float* __restrict__ bias, float* __restrict__ out) {
    extern __shared__ __align__(1024) char smem[];
    uint32_t sb = smem_u32(smem);
    const uint32_t data0 = sb + 1024;

    int tid = threadIdx.x;
    int wid = tid >> 5, lane = tid & 31;
    int warp_m = wid & 1;
    int warp_n = wid >> 1;

    int bid = blockIdx.x;
    bool is_rem = bid >= NORMAL_TILES;
    int ri = bid - NORMAL_TILES;
    int gt = is_rem ? NORMAL_TILES + (ri % REM_TILES) : bid;
    int khalf = is_rem ? (ri / REM_TILES) : 0;
    int nchunks = is_rem ? 32 : 64;
    int kc0 = khalf * 32;

    int m_base = (gt & 31) * BM;
    int n_base = (gt >> 5) * BN;

    if (tid == 0) {
#pragma unroll
        for (int s = 0; s < STAGES; s++) {
            MBARRIER_INIT(sb + s * 8, 256);       // full
            MBARRIER_INIT(sb + 32 + s * 8, 8);    // empty
        }
    }
    __syncthreads();

    // prologue
#pragma unroll
    for (int s = 0; s < STAGES; s++) {
        copy_stage(data0 + s * STAGE_BYTES, m_base, n_base, (kc0 + s) * BK, tid);
        CP_ARRIVE_NOINC(sb + s * 8);
    }

    float acc[4][4][4];
#pragma unroll
    for (int i = 0; i < 4; i++)
#pragma unroll
        for (int j = 0; j < 4; j++)
#pragma unroll
            for (int c = 0; c < 4; c++) acc[i][j][c] = 0.0f;

    const int a_row0 = warp_m * 64 + (lane & 15);
    const int a_col0 = (lane >> 4) * 16;
    const int b_row0 = warp_n * 32 + ((lane >> 4) << 3) + (lane & 7);
    const int b_col0 = ((lane >> 3) & 1) * 16;

    int s = 0;
    uint32_t ph = 0;

    for (int kt = 0; kt < nchunks; kt++) {
        mbar_wait(sb + s * 8, ph);   // full[s]

        uint32_t sA = data0 + s * STAGE_BYTES;
        uint32_t sB = sA + A_STAGE_BYTES;

#pragma unroll
        for (int k16 = 0; k16 < 4; k16++) {
            // B fragments first (shared by all mi)
            uint32_t b[4][2];
#pragma unroll
            for (int j = 0; j < 2; j++) {
                int row = b_row0 + j * 16;
                int col = b_col0 + k16 * 32;
                uint32_t addr = sB + row * 128 + (col ^ ((row & 7) << 4));
                ldsm_x4(b[2 * j][0], b[2 * j][1], b[2 * j + 1][0], b[2 * j + 1][1], addr);
            }
            // interleave: per mi, load A fragment then run its 4 MMAs
            // (live A window = 4 regs instead of 16)
#pragma unroll
            for (int mi = 0; mi < 4; mi++) {
                uint32_t a[4];
                int row = a_row0 + mi * 16;
                int col = a_col0 + k16 * 32;
                uint32_t addr = sA + row * 128 + (col ^ ((row & 7) << 4));
                ldsm_x4(a[0], a[1], a[2], a[3], addr);
                if (k16 == 3 && mi == 3 && lane == 0) {
                    MBARRIER_ARRIVE(sb + 32 + s * 8);   // empty[s]: all reads done
                }
#pragma unroll
                for (int nj = 0; nj < 4; nj++)
                    mma_16816(acc[mi][nj], a, b[nj]);
            }
        }

        if (kt + STAGES < nchunks) {
            mbar_wait(sb + 32 + s * 8, ph);   // empty[s]
            copy_stage(data0 + s * STAGE_BYTES, m_base, n_base,
                       (kc0 + kt + STAGES) * BK, tid);
            CP_ARRIVE_NOINC(sb + s * 8);
        }

        s++;
        if (s == STAGES) { s = 0; ph ^= 1; }
    }

    // epilogue
    const int m0 = m_base + warp_m * 64;
    const int n0 = n_base + warp_n * 32;
    if (!is_rem) {
#pragma unroll
        for (int mi = 0; mi < 4; mi++) {
#pragma unroll
            for (int nj = 0; nj < 4; nj++) {
                int m = m0 + mi * 16 + (lane >> 2);
                int n = n0 + nj * 8 + (lane & 3) * 2;
                float2 b2 = *reinterpret_cast<const float2*>(bias + n);
                float2 o0, o1;
                o0.x = acc[mi][nj][0] + b2.x;
                o0.y = acc[mi][nj][1] + b2.y;
                o1.x = acc[mi][nj][2] + b2.x;
                o1.y = acc[mi][nj][3] + b2.y;
                *reinterpret_cast<float2*>(out + (size_t)m * N_DIM + n) = o0;
                *reinterpret_cast<float2*>(out + (size_t)(m + 8) * N_DIM + n) = o1;
            }
        }
    } else {
        float bw = (khalf == 0) ? 1.0f : 0.0f;
#pragma unroll
        for (int mi = 0; mi < 4; mi++) {
#pragma unroll
            for (int nj = 0; nj < 4; nj++) {
                int m = m0 + mi * 16 + (lane >> 2);
                int n = n0 + nj * 8 + (lane & 3) * 2;
                float2 b2 = *reinterpret_cast<const float2*>(bias + n);
                atomicAdd(out + (size_t)m * N_DIM + n,     acc[mi][nj][0] + bw * b2.x);
                atomicAdd(out + (size_t)m * N_DIM + n + 1, acc[mi][nj][1] + bw * b2.y);
                atomicAdd(out + (size_t)(m + 8) * N_DIM + n,     acc[mi][nj][2] + bw * b2.x);
                atomicAdd(out + (size_t)(m + 8) * N_DIM + n + 1, acc[mi][nj][3] + bw * b2.y);
            }
        }
    }
}

// ---------------------------------------------------------------------------
extern "C" void kernel_launch(void* const* d_in, const int* in_sizes, int n_in,
                              void* d_out, int out_size) {
    const float* x    = (const float*)d_in[0];
    const int*   qw   = (const int*)d_in[1];
    const float* sc   = (const float*)d_in[2];
    const int*   qz   = (const int*)d_in[3];
    // d_in[4] = g_idx (identity k/128 grouping; folded into index math)
    const float* bias = (const float*)d_in[5];
    float* out = (float*)d_out;

    cudaFuncSetAttribute(prep_kernel, cudaFuncAttributeMaxDynamicSharedMemorySize,
                         DQ_SMEM);
    prep_kernel<<<CONVX_BLOCKS + DQ_BLOCKS + ZERO_BLOCKS, 256, DQ_SMEM>>>(
        x, qw, sc, qz, out);

    cudaFuncSetAttribute(gemm_kernel, cudaFuncAttributeMaxDynamicSharedMemorySize,
                         SMEM_TOTAL);
    gemm_kernel<<<GEMM_GRID, 256, SMEM_TOTAL>>>(bias, out);
}

// round 17
// speedup vs baseline: 1.5657x; 1.0029x over previous
#include <cuda_runtime.h>
#include <cuda_fp16.h>
#include <cstdint>

// ---------------------------------------------------------------------------
// QuantLinear: out[M,N] = x[M,K] @ dequant(qweight)[K,N] + bias[N]
// M=4096, K=4096, N=11008.  compute_103 PTX => HMMA mma.sync path.
//
// Launch 1 (prep): convx (NOW 32B/thread: 2x float4 -> 1x uint4, MLP=2)
//          + transposed dequant + zero-init of remainder tiles.
// Launch 2 (gemm): R14-proven, byte-identical: 128x128 tile, BK=64, 3-stage
//          mbarrier ring, 256 thr, warp tile 64x32, 2 CTAs/SM,
//          A-ldsm/MMA interleave; tiles 2664..2751 split-K=2 + atomicAdd.
// ---------------------------------------------------------------------------

#define M_DIM 4096
#define K_DIM 4096
#define N_DIM 11008

#define BM 128
#define BN 128
#define BK 64
#define STAGES 3
#define KCHUNKS (K_DIM / BK)            // 64
#define NTILES ((M_DIM / BM) * (N_DIM / BN))          // 2752
#define NORMAL_TILES 2664               // 9 * 296
#define REM_TILES (NTILES - NORMAL_TILES)             // 88
#define GEMM_GRID (NORMAL_TILES + 2 * REM_TILES)      // 2840
#define A_STAGE_BYTES (BM * 128)        // 16384
#define B_STAGE_BYTES (BN * 128)        // 16384
#define STAGE_BYTES (A_STAGE_BYTES + B_STAGE_BYTES)   // 32768
#define SMEM_TOTAL (1024 + STAGES * STAGE_BYTES)      // 99328

#define CONVX_BLOCKS (M_DIM * K_DIM / 2048)           // 8192 (8 floats/thread)
#define DQ_KP_BLKS (K_DIM / 8 / 32)                   // 16
#define DQ_N_BLKS (N_DIM / 64)                        // 172
#define DQ_BLOCKS (DQ_KP_BLKS * DQ_N_BLKS)            // 2752
#define ZERO_BLOCKS (REM_TILES * 16)                  // 1408
#define DQ_SMEM (64 * 33 * 16)                        // 33792 B

__device__ __half g_Wt[(size_t)N_DIM * K_DIM];  // [N][K]
__device__ __half g_Xh[(size_t)M_DIM * K_DIM];  // [M][K]

// ---------------------------------------------------------------------------
__device__ __forceinline__ uint32_t smem_u32(const void* p) {
    uint32_t a;
    asm("{ .reg .u64 t; cvta.to.shared.u64 t, %1; cvt.u32.u64 %0, t; }"
        : "=r"(a) : "l"(p));
    return a;
}

#define CP_ASYNC16(smem_addr, gptr) \
    asm volatile("cp.async.cg.shared.global [%0], [%1], 16;" \
        :: "r"(smem_addr), "l"(__cvta_generic_to_global(gptr)) : "memory")

#define MBARRIER_INIT(addr, cnt) \
    asm volatile("mbarrier.init.shared.b64 [%0], %1;" :: "r"(addr), "r"(cnt) : "memory")

#define CP_ARRIVE_NOINC(addr) \
    asm volatile("cp.async.mbarrier.arrive.noinc.shared.b64 [%0];" \
        :: "r"(addr) : "memory")

#define MBARRIER_ARRIVE(addr) \
    asm volatile("mbarrier.arrive.shared.b64 _, [%0];" :: "r"(addr) : "memory")

__device__ __forceinline__ void mbar_wait(uint32_t mbar, uint32_t phase) {
    asm volatile(
        "{\n\t"
        ".reg .pred P;\n\t"
        "LAB_WAIT_%=:\n\t"
        "mbarrier.try_wait.parity.shared.b64 P, [%0], %1, 0x989680;\n\t"
        "@P bra.uni LAB_DONE_%=;\n\t"
        "bra.uni LAB_WAIT_%=;\n\t"
        "LAB_DONE_%=:\n\t"
        "}"
        :: "r"(mbar), "r"(phase) : "memory");
}

__device__ __forceinline__ void ldsm_x4(uint32_t& r0, uint32_t& r1,
                                        uint32_t& r2, uint32_t& r3, uint32_t addr) {
    asm volatile("ldmatrix.sync.aligned.m8n8.x4.shared.b16 {%0,%1,%2,%3}, [%4];"
                 : "=r"(r0), "=r"(r1), "=r"(r2), "=r"(r3) : "r"(addr));
}

__device__ __forceinline__ void mma_16816(float* c, const uint32_t* a, const uint32_t* b) {
    asm volatile(
        "mma.sync.aligned.m16n8k16.row.col.f32.f16.f16.f32 "
        "{%0,%1,%2,%3}, {%4,%5,%6,%7}, {%8,%9}, {%0,%1,%2,%3};"
        : "+f"(c[0]), "+f"(c[1]), "+f"(c[2]), "+f"(c[3])
        : "r"(a[0]), "r"(a[1]), "r"(a[2]), "r"(a[3]), "r"(b[0]), "r"(b[1]));
}

// ---------------------------------------------------------------------------
// Launch 1: fused prep (convx + transposed dequant + remainder-tile zeroing).
// ---------------------------------------------------------------------------
__global__ void __launch_bounds__(256)
prep_kernel(const float* __restrict__ x,
            const int* __restrict__ qw,
            const float* __restrict__ sc,
            const int* __restrict__ qz,
            float* __restrict__ out) {
    extern __shared__ uint4 ds[];   // [64 n][33 kp] 16B entries (dequant only)
    int b = blockIdx.x;
    int tid = threadIdx.x;

    if (b < CONVX_BLOCKS) {
        // 8 floats per thread: two consecutive float4 loads, one uint4 store
        size_t i = ((size_t)b * 256 + tid) * 8;
        float4 v0 = *reinterpret_cast<const float4*>(x + i);
        float4 v1 = *reinterpret_cast<const float4*>(x + i + 4);
        __half2 h0 = __floats2half2_rn(v0.x, v0.y);
        __half2 h1 = __floats2half2_rn(v0.z, v0.w);
        __half2 h2 = __floats2half2_rn(v1.x, v1.y);
        __half2 h3 = __floats2half2_rn(v1.z, v1.w);
        uint4 u;
        u.x = *reinterpret_cast<uint32_t*>(&h0);
        u.y = *reinterpret_cast<uint32_t*>(&h1);
        u.z = *reinterpret_cast<uint32_t*>(&h2);
        u.w = *reinterpret_cast<uint32_t*>(&h3);
        *reinterpret_cast<uint4*>(&g_Xh[i]) = u;
        return;
    }

    if (b >= CONVX_BLOCKS + DQ_BLOCKS) {
        int zb = b - CONVX_BLOCKS - DQ_BLOCKS;   // 0..1407
        int gt = NORMAL_TILES + (zb >> 4);
        int within = zb & 15;
        int m0 = (gt & 31) * BM;
        int n0 = (gt >> 5) * BN;
        int idx = within * 1024 + tid * 4;
        int r = idx >> 7, c = idx & 127;
        float4 z = {0.f, 0.f, 0.f, 0.f};
        *reinterpret_cast<float4*>(out + (size_t)(m0 + r) * N_DIM + n0 + c) = z;
        return;
    }

    int db = b - CONVX_BLOCKS;
    int kp0 = (db % DQ_KP_BLKS) * 32;
    int n0  = (db / DQ_KP_BLKS) * 64;

#pragma unroll
    for (int i = 0; i < 8; i++) {
        int idx = i * 256 + tid;
        int nl = idx & 63, kl = idx >> 6;   // kl 0..31
        int kp = kp0 + kl;
        int n  = n0 + nl;
        int w32 = qw[(size_t)kp * N_DIM + n];
        int g = kp >> 4;
        float s = sc[(size_t)g * N_DIM + n];
        int zw = qz[(size_t)g * (N_DIM / 8) + (n >> 3)];
        int zq = ((zw >> ((n & 7) * 4)) & 15) + 1;
        __half2 h[4];
#pragma unroll
        for (int j = 0; j < 4; j++) {
            float v0 = s * (float)(((w32 >> (8 * j))     & 15) - zq);
            float v1 = s * (float)(((w32 >> (8 * j + 4)) & 15) - zq);
            h[j] = __floats2half2_rn(v0, v1);
        }
        ds[nl * 33 + kl] = *reinterpret_cast<uint4*>(h);
    }
    __syncthreads();
#pragma unroll
    for (int i = 0; i < 8; i++) {
        int idx = i * 256 + tid;
        int nl = idx >> 5, kl = idx & 31;   // nl 0..63
        *reinterpret_cast<uint4*>(
            &g_Wt[(size_t)(n0 + nl) * K_DIM + (size_t)(kp0 + kl) * 8]) =
            ds[nl * 33 + kl];
    }
}

// ---------------------------------------------------------------------------
// Launch 2: GEMM + split-K remainder (R14 structure, byte-identical).
// ---------------------------------------------------------------------------
__device__ __forceinline__ void copy_stage(uint32_t dst, int m_base, int n_base,
                                           int k0, int tid) {
    const __half* Ab = g_Xh + (size_t)m_base * K_DIM + k0;
    const __half* Bb = g_Wt + (size_t)n_base * K_DIM + k0;
#pragma unroll
    for (int i = 0; i < 4; i++) {
        int c = tid + i * 256;
        int row = c >> 3, col = (c & 7) * 16;
        uint32_t sw = (uint32_t)(row * 128 + (col ^ ((row & 7) << 4)));
        CP_ASYNC16(dst + sw, (const char*)Ab + (size_t)row * (K_DIM * 2) + col);
    }
#pragma unroll
    for (int i = 0; i < 4; i++) {
        int c = tid + i * 256;
        int row = c >> 3, col = (c & 7) * 16;
        uint32_t sw = (uint32_t)(row * 128 + (col ^ ((row & 7) << 4)));
        CP_ASYNC16(dst + A_STAGE_BYTES + sw,
                   (const char*)Bb + (size_t)row * (K_DIM * 2) + col);
    }
}

__global__ void __launch_bounds__(256, 2)
gemm_kernel(const float* __restrict__ bias, float* __restrict__ out) {
    extern __shared__ __align__(1024) char smem[];
    uint32_t sb = smem_u32(smem);
    const uint32_t data0 = sb + 1024;

    int tid = threadIdx.x;
    int wid = tid >> 5, lane = tid & 31;
    int warp_m = wid & 1;
    int warp_n = wid >> 1;

    int bid = blockIdx.x;
    bool is_rem = bid >= NORMAL_TILES;
    int ri = bid - NORMAL_TILES;
    int gt = is_rem ? NORMAL_TILES + (ri % REM_TILES) : bid;
    int khalf = is_rem ? (ri / REM_TILES) : 0;
    int nchunks = is_rem ? 32 : 64;
    int kc0 = khalf * 32;

    int m_base = (gt & 31) * BM;
    int n_base = (gt >> 5) * BN;

    if (tid == 0) {
#pragma unroll
        for (int s = 0; s < STAGES; s++) {
            MBARRIER_INIT(sb + s * 8, 256);       // full
            MBARRIER_INIT(sb + 32 + s * 8, 8);    // empty
        }
    }
    __syncthreads();

    // prologue
#pragma unroll
    for (int s = 0; s < STAGES; s++) {
        copy_stage(data0 + s * STAGE_BYTES, m_base, n_base, (kc0 + s) * BK, tid);
        CP_ARRIVE_NOINC(sb + s * 8);
    }

    float acc[4][4][4];
#pragma unroll
    for (int i = 0; i < 4; i++)
#pragma unroll
        for (int j = 0; j < 4; j++)
#pragma unroll
            for (int c = 0; c < 4; c++) acc[i][j][c] = 0.0f;

    const int a_row0 = warp_m * 64 + (lane & 15);
    const int a_col0 = (lane >> 4) * 16;
    const int b_row0 = warp_n * 32 + ((lane >> 4) << 3) + (lane & 7);
    const int b_col0 = ((lane >> 3) & 1) * 16;

    int s = 0;
    uint32_t ph = 0;

    for (int kt = 0; kt < nchunks; kt++) {
        mbar_wait(sb + s * 8, ph);   // full[s]

        uint32_t sA = data0 + s * STAGE_BYTES;
        uint32_t sB = sA + A_STAGE_BYTES;

#pragma unroll
        for (int k16 = 0; k16 < 4; k16++) {
            // B fragments first (shared by all mi)
            uint32_t b[4][2];
#pragma unroll
            for (int j = 0; j < 2; j++) {
                int row = b_row0 + j * 16;
                int col = b_col0 + k16 * 32;
                uint32_t addr = sB + row * 128 + (col ^ ((row & 7) << 4));
                ldsm_x4(b[2 * j][0], b[2 * j][1], b[2 * j + 1][0], b[2 * j + 1][1], addr);
            }
            // interleave: per mi, load A fragment then run its 4 MMAs
#pragma unroll
            for (int mi = 0; mi < 4; mi++) {
                uint32_t a[4];
                int row = a_row0 + mi * 16;
                int col = a_col0 + k16 * 32;
                uint32_t addr = sA + row * 128 + (col ^ ((row & 7) << 4));
                ldsm_x4(a[0], a[1], a[2], a[3], addr);
                if (k16 == 3 && mi == 3 && lane == 0) {
                    MBARRIER_ARRIVE(sb + 32 + s * 8);   // empty[s]: all reads done
                }
#pragma unroll
                for (int nj = 0; nj < 4; nj++)
                    mma_16816(acc[mi][nj], a, b[nj]);
            }
        }

        if (kt + STAGES < nchunks) {
            mbar_wait(sb + 32 + s * 8, ph);   // empty[s]
            copy_stage(data0 + s * STAGE_BYTES, m_base, n_base,
                       (kc0 + kt + STAGES) * BK, tid);
            CP_ARRIVE_NOINC(sb + s * 8);
        }

        s++;
        if (s == STAGES) { s = 0; ph ^= 1; }
    }

    // epilogue
    const int m0 = m_base + warp_m * 64;
    const int n0 = n_base + warp_n * 32;
    if (!is_rem) {
#pragma unroll
        for (int mi = 0; mi < 4; mi++) {
#pragma unroll
            for (int nj = 0; nj < 4; nj++) {
                int m = m0 + mi * 16 + (lane >> 2);
                int n = n0 + nj * 8 + (lane & 3) * 2;
                float2 b2 = *reinterpret_cast<const float2*>(bias + n);
                float2 o0, o1;
                o0.x = acc[mi][nj][0] + b2.x;
                o0.y = acc[mi][nj][1] + b2.y;
                o1.x = acc[mi][nj][2] + b2.x;
                o1.y = acc[mi][nj][3] + b2.y;
                *reinterpret_cast<float2*>(out + (size_t)m * N_DIM + n) = o0;
                *reinterpret_cast<float2*>(out + (size_t)(m + 8) * N_DIM + n) = o1;
            }
        }
    } else {
        float bw = (khalf == 0) ? 1.0f : 0.0f;
#pragma unroll
        for (int mi = 0; mi < 4; mi++) {
#pragma unroll
            for (int nj = 0; nj < 4; nj++) {
                int m = m0 + mi * 16 + (lane >> 2);
                int n = n0 + nj * 8 + (lane & 3) * 2;
                float2 b2 = *reinterpret_cast<const float2*>(bias + n);
                atomicAdd(out + (size_t)m * N_DIM + n,     acc[mi][nj][0] + bw * b2.x);
                atomicAdd(out + (size_t)m * N_DIM + n + 1, acc[mi][nj][1] + bw * b2.y);
                atomicAdd(out + (size_t)(m + 8) * N_DIM + n,     acc[mi][nj][2] + bw * b2.x);
                atomicAdd(out + (size_t)(m + 8) * N_DIM + n + 1, acc[mi][nj][3] + bw * b2.y);
            }
        }
    }
}

// ---------------------------------------------------------------------------
extern "C" void kernel_launch(void* const* d_in, const int* in_sizes, int n_in,
                              void* d_out, int out_size) {
    const float* x    = (const float*)d_in[0];
    const int*   qw   = (const int*)d_in[1];
    const float* sc   = (const float*)d_in[2];
    const int*   qz   = (const int*)d_in[3];
    // d_in[4] = g_idx (identity k/128 grouping; folded into index math)
    const float* bias = (const float*)d_in[5];
    float* out = (float*)d_out;

    cudaFuncSetAttribute(prep_kernel, cudaFuncAttributeMaxDynamicSharedMemorySize,
                         DQ_SMEM);
    prep_kernel<<<CONVX_BLOCKS + DQ_BLOCKS + ZERO_BLOCKS, 256, DQ_SMEM>>>(
        x, qw, sc, qz, out);

    cudaFuncSetAttribute(gemm_kernel, cudaFuncAttributeMaxDynamicSharedMemorySize,
                         SMEM_TOTAL);
    gemm_kernel<<<GEMM_GRID, 256, SMEM_TOTAL>>>(bias, out);
}